// round 2
// baseline (speedup 1.0000x reference)
#include <cuda_runtime.h>
#include <math.h>

// GAT layer: B=32768, N=12, F=256, D=128
// inputs: x [B,N,F] f32, adj [N,N] f32, W [F,D] f32, a [2D,1] f32
// out: [B,N,D] f32
//
// Fully fused per-b pipeline: H = x_b @ W kept in smem, attention + softmax +
// alpha@H + elu computed in-CTA, only x read and out written to HBM.

#define B_TOT 32768
#define NN    12
#define FF    256
#define DDIM  128
#define NB    4            // b-values per CTA iteration
#define NTHREADS 256
#define GRID_X 1024
#define ITERS ((B_TOT / NB) / GRID_X)   // 8

// smem layout (floats)
#define W_OFF   0            // [256][128]   32768
#define X_OFF   32768        // [NB][12][256] 12288
#define H_OFF   45056        // [NB][12][128] 6144
#define A_OFF   51200        // [256]
#define ADJ_OFF 51456        // [144]
#define S1_OFF  51600        // [NB*12]
#define S2_OFF  51648        // [NB*12]
#define AL_OFF  51696        // [NB][12][12] 576
#define SMEM_FLOATS 52272
#define SMEM_BYTES (SMEM_FLOATS * 4)     // 209088 B

extern __shared__ float smem[];

__global__ __launch_bounds__(NTHREADS, 1)
void gat_fused_kernel(const float* __restrict__ x,
                      const float* __restrict__ adj,
                      const float* __restrict__ W,
                      const float* __restrict__ a,
                      float* __restrict__ out)
{
    float* sW   = smem + W_OFF;
    float* sX   = smem + X_OFF;
    float* sH   = smem + H_OFF;
    float* sA   = smem + A_OFF;
    float* sAdj = smem + ADJ_OFF;
    float* sS1  = smem + S1_OFF;
    float* sS2  = smem + S2_OFF;
    float* sAl  = smem + AL_OFF;

    const int t = threadIdx.x;

    // ---- one-time loads: W (128KB), a, adj ----
    {
        const float4* Wg = (const float4*)W;
        float4* sW4 = (float4*)sW;
        #pragma unroll
        for (int i = 0; i < (FF * DDIM / 4) / NTHREADS; ++i)
            sW4[t + i * NTHREADS] = Wg[t + i * NTHREADS];
        if (t < 256) sA[t] = a[t];
        if (t < 144) sAdj[t] = adj[t];
    }
    __syncthreads();

    // GEMM thread mapping: 6 rows x 4 cols per thread
    const int dg = t & 31;          // col group: cols 4*dg .. 4*dg+3
    const int ig = (t >> 5) & 1;    // row group: rows 6*ig .. 6*ig+5
    const int bb = t >> 6;          // which of NB b's

    for (int it = 0; it < ITERS; ++it) {
        const int b0 = (blockIdx.x * ITERS + it) * NB;

        // ---- stage x for NB b's ----
        {
            const float4* xg = (const float4*)(x + (size_t)b0 * NN * FF);
            float4* sX4 = (float4*)sX;
            #pragma unroll
            for (int i = 0; i < (NB * NN * FF / 4) / NTHREADS; ++i)
                sX4[t + i * NTHREADS] = xg[t + i * NTHREADS];
        }
        __syncthreads();

        // ---- H = x_b @ W  (register-tiled) ----
        {
            float acc[6][4];
            #pragma unroll
            for (int r = 0; r < 6; ++r)
                #pragma unroll
                for (int c = 0; c < 4; ++c) acc[r][c] = 0.f;

            const float* xrow = sX + (bb * NN + 6 * ig) * FF;
            const float4* w4 = (const float4*)sW;   // [256][32] of float4

            #pragma unroll 4
            for (int k = 0; k < FF; ++k) {
                float4 w = w4[k * 32 + dg];
                #pragma unroll
                for (int r = 0; r < 6; ++r) {
                    float xv = xrow[r * FF + k];
                    acc[r][0] = fmaf(xv, w.x, acc[r][0]);
                    acc[r][1] = fmaf(xv, w.y, acc[r][1]);
                    acc[r][2] = fmaf(xv, w.z, acc[r][2]);
                    acc[r][3] = fmaf(xv, w.w, acc[r][3]);
                }
            }
            #pragma unroll
            for (int r = 0; r < 6; ++r) {
                float4 v = make_float4(acc[r][0], acc[r][1], acc[r][2], acc[r][3]);
                *(float4*)(sH + (bb * NN + 6 * ig + r) * DDIM + 4 * dg) = v;
            }
        }
        __syncthreads();

        // ---- s1 = H @ a[:D]  (neighbor term), s2 = H @ a[D:] (node term) ----
        {
            const int wid = t >> 5, lane = t & 31;
            #pragma unroll
            for (int pi = 0; pi < 6; ++pi) {
                const int p = wid * 6 + pi;          // p = b*12 + n, 48 total
                const float* hrow = sH + p * DDIM;
                float v1 = 0.f, v2 = 0.f;
                #pragma unroll
                for (int dd = 0; dd < DDIM; dd += 32) {
                    float h = hrow[dd + lane];
                    v1 = fmaf(h, sA[dd + lane], v1);
                    v2 = fmaf(h, sA[DDIM + dd + lane], v2);
                }
                #pragma unroll
                for (int o = 16; o > 0; o >>= 1) {
                    v1 += __shfl_xor_sync(0xffffffffu, v1, o);
                    v2 += __shfl_xor_sync(0xffffffffu, v2, o);
                }
                if (lane == 0) { sS1[p] = v1; sS2[p] = v2; }
            }
        }
        __syncthreads();

        // ---- masked softmax rows -> alpha ----
        if (t < NB * NN) {
            const int pb = t / NN, i = t % NN;
            const float si = sS2[pb * NN + i];
            float e[NN];
            float m = -1e30f;
            #pragma unroll
            for (int j = 0; j < NN; ++j) {
                float v = si + sS1[pb * NN + j];
                v = v >= 0.f ? v : 0.2f * v;                 // leaky_relu 0.2
                const bool msk = (sAdj[i * NN + j] == 1.0f);
                e[j] = msk ? v : -1e30f;
                m = fmaxf(m, e[j]);
            }
            float s = 0.f;
            #pragma unroll
            for (int j = 0; j < NN; ++j) {
                float p_ = (e[j] > -1e29f) ? expf(e[j] - m) : 0.f;
                e[j] = p_;
                s += p_;
            }
            const float inv = 1.0f / s;
            #pragma unroll
            for (int j = 0; j < NN; ++j)
                sAl[(pb * NN + i) * NN + j] = e[j] * inv;
        }
        __syncthreads();

        // ---- h' = alpha @ H ; elu ; store ----
        {
            const int d = t & 127, g = t >> 7;    // g in {0,1}: rows 0..23 / 24..47
            #pragma unroll
            for (int rr = 0; rr < 24; ++rr) {
                const int row = g * 24 + rr;      // row = local_b*12 + i
                const int pb = row / NN;
                const float* al = sAl + row * NN;
                const float* hb = sH + pb * NN * DDIM + d;
                float acc2 = 0.f;
                #pragma unroll
                for (int j = 0; j < NN; ++j)
                    acc2 = fmaf(al[j], hb[j * DDIM], acc2);
                const float o = acc2 > 0.f ? acc2 : (expf(acc2) - 1.0f);
                out[((size_t)b0 * NN + row) * DDIM + d] = o;
            }
        }
        __syncthreads();   // protect sX/sH before next iteration
    }
}

extern "C" void kernel_launch(void* const* d_in, const int* in_sizes, int n_in,
                              void* d_out, int out_size)
{
    const float* x   = (const float*)d_in[0];
    const float* adj = (const float*)d_in[1];
    const float* W   = (const float*)d_in[2];
    const float* a   = (const float*)d_in[3];
    float* out = (float*)d_out;

    static int configured = 0;
    if (!configured) {
        cudaFuncSetAttribute(gat_fused_kernel,
                             cudaFuncAttributeMaxDynamicSharedMemorySize, SMEM_BYTES);
        configured = 1;
    }
    gat_fused_kernel<<<GRID_X, NTHREADS, SMEM_BYTES>>>(x, adj, W, a, out);
}

// round 6
// speedup vs baseline: 2.1996x; 2.1996x over previous
#include <cuda_runtime.h>
#include <cuda_bf16.h>
#include <math.h>
#include <stdint.h>

// GAT layer, GB300 (base-ISA only: compute_103 PTX -> no tcgen05/TMA).
// B=32768, N=12, F=256, D=128, fp32 in/out.
// H = X@W via mma.sync bf16 split GEMM (xh*wh + xh*wl + xl*wh), fused
// attention epilogue in-CTA. Per CTA: 16 b's = 192 rows, K=256.

#define NN      12
#define FF      256
#define DD      128
#define BBATCH  16
#define ROWS    192          // BBATCH * NN
#define NTH     256
#define GRID    2048         // 32768 / 16
#define KC      64
#define NCHUNK  4            // FF / KC

// padded pitches (bf16 elems) -> byte stride ≡ 16 mod 128: conflict-free ldmatrix
#define XPITCH  72           // 144 B rows, chunk k=64
#define WPITCH  264          // 528 B rows, full k=256

// ---- smem byte offsets (phase 1: GEMM operands) ----
#define XHI_OFF 0                                  // [192][72] bf16 = 27648
#define XLO_OFF 27648
#define WHI_OFF 55296                              // [128][264] bf16 = 67584
#define WLO_OFF 122880
#define SMEM_BYTES 190464
// ---- phase 2 overlay (after GEMM) ----
#define H_OFF     0          // [192][132] f32 = 101376
#define HSTRIDE   132
#define SA_OFF    101376     // 256 f32
#define SADJ_OFF  102400     // 144 f32
#define SS1_OFF   102976     // 192 f32
#define SS2_OFF   103744     // 192 f32
#define SAL_OFF   104512     // [192][12] f32

static __device__ __forceinline__ uint32_t smem_addr_u32(const void* p) {
    uint32_t r;
    asm("{ .reg .u64 t; cvta.to.shared.u64 t, %1; cvt.u32.u64 %0, t; }" : "=r"(r) : "l"(p));
    return r;
}

static __device__ __forceinline__ uint32_t pack_bf2(__nv_bfloat16 a, __nv_bfloat16 b) {
    __nv_bfloat162 h; h.x = a; h.y = b;
    return *reinterpret_cast<uint32_t*>(&h);
}

static __device__ __forceinline__ void split_f32(float v, __nv_bfloat16& hi, __nv_bfloat16& lo) {
    hi = __float2bfloat16_rn(v);
    lo = __float2bfloat16_rn(v - __bfloat162float(hi));
}

static __device__ __forceinline__ void ldsm_x4(uint32_t* r, uint32_t addr) {
    asm volatile("ldmatrix.sync.aligned.m8n8.x4.shared.b16 {%0,%1,%2,%3}, [%4];"
                 : "=r"(r[0]), "=r"(r[1]), "=r"(r[2]), "=r"(r[3]) : "r"(addr));
}

static __device__ __forceinline__ void mma_bf16(float* d, const uint32_t* a, const uint32_t* b) {
    asm volatile(
        "mma.sync.aligned.m16n8k16.row.col.f32.bf16.bf16.f32 "
        "{%0,%1,%2,%3}, {%4,%5,%6,%7}, {%8,%9}, {%0,%1,%2,%3};"
        : "+f"(d[0]), "+f"(d[1]), "+f"(d[2]), "+f"(d[3])
        : "r"(a[0]), "r"(a[1]), "r"(a[2]), "r"(a[3]), "r"(b[0]), "r"(b[1]));
}

extern __shared__ __align__(1024) char smc[];

__global__ __launch_bounds__(NTH, 1)
void gat_hmma_kernel(const float* __restrict__ x,
                     const float* __restrict__ adj,
                     const float* __restrict__ W,
                     const float* __restrict__ a,
                     float* __restrict__ out)
{
    const int tid  = threadIdx.x;
    const int wid  = tid >> 5;
    const int lane = tid & 31;
    const int b0   = blockIdx.x * BBATCH;

    const uint32_t smem_base = smem_addr_u32(smc);

    // ---- stage W once: gmem [256 k][128 n] f32 -> smem W^T [n][k] bf16 hi/lo ----
    {
        const int n    = tid & 127;
        const int half = tid >> 7;                 // k range half*128..+128
        #pragma unroll 16
        for (int k2 = 0; k2 < 128; k2 += 2) {
            const int k = half * 128 + k2;
            float w0 = W[(size_t)k * DD + n];
            float w1 = W[(size_t)(k + 1) * DD + n];
            __nv_bfloat16 h0, l0, h1, l1;
            split_f32(w0, h0, l0);
            split_f32(w1, h1, l1);
            const uint32_t off = (uint32_t)n * (WPITCH * 2) + k * 2;
            *(uint32_t*)(smc + WHI_OFF + off) = pack_bf2(h0, h1);
            *(uint32_t*)(smc + WLO_OFF + off) = pack_bf2(l0, l1);
        }
    }

    // ---- GEMM: acc[m][n][4], warp tile 48 rows x 64 cols ----
    const int rg = wid >> 1;     // 0..3 : rows rg*48..+48
    const int cg = wid & 1;      // 0..1 : cols cg*64..+64

    float acc[3][8][4];
    #pragma unroll
    for (int m = 0; m < 3; ++m)
        #pragma unroll
        for (int n = 0; n < 8; ++n)
            #pragma unroll
            for (int q = 0; q < 4; ++q) acc[m][n][q] = 0.f;

    // ldmatrix lane address components (constant per thread)
    const int a_row_l = (lane & 7) + ((lane >> 3) & 1) * 8;   // + m0
    const int a_k_l   = (lane >> 4) * 8;                       // + ks*16
    const int b_n_l   = (lane & 7) + (lane >> 4) * 8;          // + nbase
    const int b_k_l   = ((lane >> 3) & 1) * 8;                 // + kglob

    const float4* xg4 = (const float4*)x;
    const size_t rowbase4 = (size_t)b0 * NN * (FF / 4);

    for (int c = 0; c < NCHUNK; ++c) {
        // stage x chunk: 192 rows x 64 f32 -> bf16 hi/lo, pitch 72
        #pragma unroll
        for (int i = 0; i < (ROWS * (KC / 4)) / NTH; ++i) {    // 12 iters
            const int idx = tid + i * NTH;
            const int r   = idx >> 4;
            const int c4  = idx & 15;
            float4 v = xg4[rowbase4 + (size_t)r * (FF / 4) + c * (KC / 4) + c4];
            __nv_bfloat16 hx, lx, hy, ly, hz, lz, hw, lw;
            split_f32(v.x, hx, lx); split_f32(v.y, hy, ly);
            split_f32(v.z, hz, lz); split_f32(v.w, hw, lw);
            const uint32_t off = (uint32_t)r * (XPITCH * 2) + c4 * 8;
            *(uint2*)(smc + XHI_OFF + off) = make_uint2(pack_bf2(hx, hy), pack_bf2(hz, hw));
            *(uint2*)(smc + XLO_OFF + off) = make_uint2(pack_bf2(lx, ly), pack_bf2(lz, lw));
        }
        __syncthreads();

        #pragma unroll
        for (int ks = 0; ks < KC / 16; ++ks) {                 // 4 k16-steps
            const int kglob = c * KC + ks * 16;
            // B fragments: 8 n8-tiles, hi & lo
            uint32_t bhi[8][2], blo[8][2];
            #pragma unroll
            for (int p = 0; p < 4; ++p) {
                const int nbase = cg * 64 + p * 16;
                const uint32_t boff =
                    (uint32_t)(nbase + b_n_l) * (WPITCH * 2) + (kglob + b_k_l) * 2;
                uint32_t r4[4];
                ldsm_x4(r4, smem_base + WHI_OFF + boff);
                bhi[2*p][0] = r4[0]; bhi[2*p][1] = r4[1];
                bhi[2*p+1][0] = r4[2]; bhi[2*p+1][1] = r4[3];
                ldsm_x4(r4, smem_base + WLO_OFF + boff);
                blo[2*p][0] = r4[0]; blo[2*p][1] = r4[1];
                blo[2*p+1][0] = r4[2]; blo[2*p+1][1] = r4[3];
            }
            #pragma unroll
            for (int m = 0; m < 3; ++m) {
                const int m0 = rg * 48 + m * 16;
                const uint32_t aoff =
                    (uint32_t)(m0 + a_row_l) * (XPITCH * 2) + (ks * 16 + a_k_l) * 2;
                uint32_t ahi[4], alo[4];
                ldsm_x4(ahi, smem_base + XHI_OFF + aoff);
                ldsm_x4(alo, smem_base + XLO_OFF + aoff);
                #pragma unroll
                for (int n = 0; n < 8; ++n) mma_bf16(acc[m][n], ahi, bhi[n]);
                #pragma unroll
                for (int n = 0; n < 8; ++n) mma_bf16(acc[m][n], ahi, blo[n]);
                #pragma unroll
                for (int n = 0; n < 8; ++n) mma_bf16(acc[m][n], alo, bhi[n]);
            }
        }
        __syncthreads();    // x chunk buffers free for next stage
    }

    // ---- store H tiles: acc -> smem [192][132] f32 (overlays GEMM buffers) ----
    float* sH = (float*)(smc + H_OFF);
    {
        const int qr = lane >> 2;          // 0..7
        const int qc = (lane & 3) * 2;     // 0,2,4,6
        #pragma unroll
        for (int m = 0; m < 3; ++m) {
            const int row = rg * 48 + m * 16 + qr;
            #pragma unroll
            for (int n = 0; n < 8; ++n) {
                const int col = cg * 64 + n * 8 + qc;
                *(float2*)(sH + row * HSTRIDE + col) =
                    make_float2(acc[m][n][0], acc[m][n][1]);
                *(float2*)(sH + (row + 8) * HSTRIDE + col) =
                    make_float2(acc[m][n][2], acc[m][n][3]);
            }
        }
    }
    float* sA   = (float*)(smc + SA_OFF);
    float* sAdj = (float*)(smc + SADJ_OFF);
    float* sS1  = (float*)(smc + SS1_OFF);
    float* sS2  = (float*)(smc + SS2_OFF);
    float* sAl  = (float*)(smc + SAL_OFF);
    if (tid < 2 * DD) sA[tid] = a[tid];
    if (tid < NN * NN) sAdj[tid] = adj[tid];
    __syncthreads();

    // ---- s1 = H @ a[:D], s2 = H @ a[D:] : 24 rows per warp ----
    {
        #pragma unroll
        for (int pi = 0; pi < ROWS / 8; ++pi) {
            const int p = wid * (ROWS / 8) + pi;
            const float* hrow = sH + p * HSTRIDE;
            float v1 = 0.f, v2 = 0.f;
            #pragma unroll
            for (int dd = 0; dd < DD; dd += 32) {
                float h = hrow[dd + lane];
                v1 = fmaf(h, sA[dd + lane], v1);
                v2 = fmaf(h, sA[DD + dd + lane], v2);
            }
            #pragma unroll
            for (int o = 16; o > 0; o >>= 1) {
                v1 += __shfl_xor_sync(0xffffffffu, v1, o);
                v2 += __shfl_xor_sync(0xffffffffu, v2, o);
            }
            if (lane == 0) { sS1[p] = v1; sS2[p] = v2; }
        }
    }
    __syncthreads();

    // ---- masked softmax: threads 0..191 ----
    if (tid < ROWS) {
        const int pb = tid / NN, i = tid % NN;
        const float si = sS2[tid];
        float e[NN];
        float m = -1e30f;
        #pragma unroll
        for (int j = 0; j < NN; ++j) {
            float v = si + sS1[pb * NN + j];
            v = v >= 0.f ? v : 0.2f * v;                  // leaky_relu 0.2
            e[j] = (sAdj[i * NN + j] == 1.0f) ? v : -1e30f;
            m = fmaxf(m, e[j]);
        }
        float s = 0.f;
        #pragma unroll
        for (int j = 0; j < NN; ++j) {
            float p_ = (e[j] > -1e29f) ? expf(e[j] - m) : 0.f;
            e[j] = p_;
            s += p_;
        }
        const float inv = 1.0f / s;
        #pragma unroll
        for (int j = 0; j < NN; ++j)
            sAl[tid * NN + j] = e[j] * inv;
    }
    __syncthreads();

    // ---- h' = alpha @ H, elu, store. Each warp: 2 b's, H[b] cached in regs ----
    {
        const int d0 = lane * 4;
        #pragma unroll
        for (int q = 0; q < 2; ++q) {
            const int b = wid * 2 + q;            // 0..15
            const int rowb = b * NN;
            float4 h[NN];
            #pragma unroll
            for (int j = 0; j < NN; ++j)
                h[j] = *(const float4*)(sH + (rowb + j) * HSTRIDE + d0);
            #pragma unroll
            for (int i = 0; i < NN; ++i) {
                const float* al = sAl + (rowb + i) * NN;
                float4 o4 = make_float4(0.f, 0.f, 0.f, 0.f);
                #pragma unroll
                for (int j = 0; j < NN; ++j) {
                    const float aij = al[j];
                    o4.x = fmaf(aij, h[j].x, o4.x);
                    o4.y = fmaf(aij, h[j].y, o4.y);
                    o4.z = fmaf(aij, h[j].z, o4.z);
                    o4.w = fmaf(aij, h[j].w, o4.w);
                }
                o4.x = o4.x > 0.f ? o4.x : (expf(o4.x) - 1.f);
                o4.y = o4.y > 0.f ? o4.y : (expf(o4.y) - 1.f);
                o4.z = o4.z > 0.f ? o4.z : (expf(o4.z) - 1.f);
                o4.w = o4.w > 0.f ? o4.w : (expf(o4.w) - 1.f);
                *(float4*)(out + ((size_t)(b0 + b) * NN + i) * DD + d0) = o4;
            }
        }
    }
}

extern "C" void kernel_launch(void* const* d_in, const int* in_sizes, int n_in,
                              void* d_out, int out_size)
{
    const float* x   = (const float*)d_in[0];
    const float* adj = (const float*)d_in[1];
    const float* W   = (const float*)d_in[2];
    const float* a   = (const float*)d_in[3];
    float* out = (float*)d_out;

    static int configured = 0;
    if (!configured) {
        cudaFuncSetAttribute(gat_hmma_kernel,
                             cudaFuncAttributeMaxDynamicSharedMemorySize, SMEM_BYTES);
        configured = 1;
    }
    gat_hmma_kernel<<<GRID, NTH, SMEM_BYTES>>>(x, adj, W, a, out);
}

// round 7
// speedup vs baseline: 2.6308x; 1.1961x over previous
#include <cuda_runtime.h>
#include <cuda_bf16.h>
#include <math.h>
#include <stdint.h>

// GAT layer, GB300 (base-ISA: mma.sync bf16 split GEMM).
// B=32768, N=12, F=256, D=128, fp32 in/out.
// R6: 16 warps/CTA (48x32 warp tiles), register-prefetch pipeline on x,
// __expf epilogue. Per CTA: 16 b's = 192 rows, K=256.

#define NN      12
#define FF      256
#define DD      128
#define BBATCH  16
#define ROWS    192          // BBATCH * NN
#define NTH     512
#define GRID    2048         // 32768 / 16
#define KC      64
#define NCHUNK  4            // FF / KC

// padded pitches (bf16 elems) -> byte stride ≡ 16 mod 128: conflict-free ldmatrix
#define XPITCH  72           // 144 B rows, chunk k=64
#define WPITCH  264          // 528 B rows, full k=256

// ---- smem byte offsets (phase 1: GEMM operands) ----
#define XHI_OFF 0                                  // [192][72] bf16 = 27648
#define XLO_OFF 27648
#define WHI_OFF 55296                              // [128][264] bf16 = 67584
#define WLO_OFF 122880
#define SMEM_BYTES 190464
// ---- phase 2 overlay (after GEMM) ----
#define H_OFF     0          // [192][132] f32 = 101376
#define HSTRIDE   132
#define SA_OFF    101376     // 256 f32
#define SADJ_OFF  102400     // 144 f32
#define SS1_OFF   102976     // 192 f32
#define SS2_OFF   103744     // 192 f32
#define SAL_OFF   104512     // [192][12] f32

#define XLD_ITERS ((ROWS * (KC / 4)) / NTH)        // 6 float4 loads per thread per chunk

static __device__ __forceinline__ uint32_t smem_addr_u32(const void* p) {
    uint32_t r;
    asm("{ .reg .u64 t; cvta.to.shared.u64 t, %1; cvt.u32.u64 %0, t; }" : "=r"(r) : "l"(p));
    return r;
}

static __device__ __forceinline__ uint32_t pack_bf2(__nv_bfloat16 a, __nv_bfloat16 b) {
    __nv_bfloat162 h; h.x = a; h.y = b;
    return *reinterpret_cast<uint32_t*>(&h);
}

static __device__ __forceinline__ void split_f32(float v, __nv_bfloat16& hi, __nv_bfloat16& lo) {
    hi = __float2bfloat16_rn(v);
    lo = __float2bfloat16_rn(v - __bfloat162float(hi));
}

static __device__ __forceinline__ void ldsm_x4(uint32_t* r, uint32_t addr) {
    asm volatile("ldmatrix.sync.aligned.m8n8.x4.shared.b16 {%0,%1,%2,%3}, [%4];"
                 : "=r"(r[0]), "=r"(r[1]), "=r"(r[2]), "=r"(r[3]) : "r"(addr));
}

static __device__ __forceinline__ void mma_bf16(float* d, const uint32_t* a, const uint32_t* b) {
    asm volatile(
        "mma.sync.aligned.m16n8k16.row.col.f32.bf16.bf16.f32 "
        "{%0,%1,%2,%3}, {%4,%5,%6,%7}, {%8,%9}, {%0,%1,%2,%3};"
        : "+f"(d[0]), "+f"(d[1]), "+f"(d[2]), "+f"(d[3])
        : "r"(a[0]), "r"(a[1]), "r"(a[2]), "r"(a[3]), "r"(b[0]), "r"(b[1]));
}

extern __shared__ __align__(1024) char smc[];

__global__ __launch_bounds__(NTH, 1)
void gat_hmma16_kernel(const float* __restrict__ x,
                       const float* __restrict__ adj,
                       const float* __restrict__ W,
                       const float* __restrict__ a,
                       float* __restrict__ out)
{
    const int tid  = threadIdx.x;
    const int wid  = tid >> 5;
    const int lane = tid & 31;
    const int b0   = blockIdx.x * BBATCH;

    const uint32_t smem_base = smem_addr_u32(smc);

    // x staging indices (fixed per thread)
    const int xr  = tid >> 4;          // row 0..191 (first 256 tids), +... via iter
    const int xc4 = tid & 15;
    const float4* xg4 = (const float4*)x;
    const size_t rowbase4 = (size_t)b0 * NN * (FF / 4);

    // ---- prefetch chunk 0 into regs ----
    float4 px[XLD_ITERS];
    #pragma unroll
    for (int i = 0; i < XLD_ITERS; ++i) {
        const int idx = tid + i * NTH;
        const int r = idx >> 4, c4 = idx & 15;
        px[i] = xg4[rowbase4 + (size_t)r * (FF / 4) + c4];
    }

    // ---- stage W once: gmem [256 k][128 n] f32 -> smem W^T [n][k] bf16 hi/lo ----
    {
        const int n  = tid & 127;
        const int kq = tid >> 7;                    // 0..3, k range kq*64..+64
        #pragma unroll 8
        for (int k2 = 0; k2 < KC; k2 += 2) {
            const int k = kq * KC + k2;
            float w0 = W[(size_t)k * DD + n];
            float w1 = W[(size_t)(k + 1) * DD + n];
            __nv_bfloat16 h0, l0, h1, l1;
            split_f32(w0, h0, l0);
            split_f32(w1, h1, l1);
            const uint32_t off = (uint32_t)n * (WPITCH * 2) + k * 2;
            *(uint32_t*)(smc + WHI_OFF + off) = pack_bf2(h0, h1);
            *(uint32_t*)(smc + WLO_OFF + off) = pack_bf2(l0, l1);
        }
    }

    // ---- GEMM: 16 warps, warp tile 48 rows x 32 cols ----
    const int rg = wid >> 2;     // 0..3 : rows rg*48..+48
    const int cg = wid & 3;      // 0..3 : cols cg*32..+32

    float acc[3][4][4];
    #pragma unroll
    for (int m = 0; m < 3; ++m)
        #pragma unroll
        for (int n = 0; n < 4; ++n)
            #pragma unroll
            for (int q = 0; q < 4; ++q) acc[m][n][q] = 0.f;

    // ldmatrix lane address components
    const int a_row_l = (lane & 7) + ((lane >> 3) & 1) * 8;
    const int a_k_l   = (lane >> 4) * 8;
    const int b_n_l   = (lane & 7) + (lane >> 4) * 8;
    const int b_k_l   = ((lane >> 3) & 1) * 8;

    for (int c = 0; c < NCHUNK; ++c) {
        // convert + store prefetched chunk, then issue next chunk's loads
        #pragma unroll
        for (int i = 0; i < XLD_ITERS; ++i) {
            const int idx = tid + i * NTH;
            const int r = idx >> 4, c4 = idx & 15;
            float4 v = px[i];
            __nv_bfloat16 hx, lx, hy, ly, hz, lz, hw, lw;
            split_f32(v.x, hx, lx); split_f32(v.y, hy, ly);
            split_f32(v.z, hz, lz); split_f32(v.w, hw, lw);
            const uint32_t off = (uint32_t)r * (XPITCH * 2) + c4 * 8;
            *(uint2*)(smc + XHI_OFF + off) = make_uint2(pack_bf2(hx, hy), pack_bf2(hz, hw));
            *(uint2*)(smc + XLO_OFF + off) = make_uint2(pack_bf2(lx, ly), pack_bf2(lz, lw));
        }
        if (c + 1 < NCHUNK) {
            #pragma unroll
            for (int i = 0; i < XLD_ITERS; ++i) {
                const int idx = tid + i * NTH;
                const int r = idx >> 4, c4 = idx & 15;
                px[i] = xg4[rowbase4 + (size_t)r * (FF / 4) + (c + 1) * (KC / 4) + c4];
            }
        }
        __syncthreads();

        #pragma unroll
        for (int ks = 0; ks < KC / 16; ++ks) {                 // 4 k16-steps
            const int kglob = c * KC + ks * 16;
            // B fragments: 4 n8-tiles, hi & lo
            uint32_t bhi[4][2], blo[4][2];
            #pragma unroll
            for (int p = 0; p < 2; ++p) {
                const int nbase = cg * 32 + p * 16;
                const uint32_t boff =
                    (uint32_t)(nbase + b_n_l) * (WPITCH * 2) + (kglob + b_k_l) * 2;
                uint32_t r4[4];
                ldsm_x4(r4, smem_base + WHI_OFF + boff);
                bhi[2*p][0] = r4[0]; bhi[2*p][1] = r4[1];
                bhi[2*p+1][0] = r4[2]; bhi[2*p+1][1] = r4[3];
                ldsm_x4(r4, smem_base + WLO_OFF + boff);
                blo[2*p][0] = r4[0]; blo[2*p][1] = r4[1];
                blo[2*p+1][0] = r4[2]; blo[2*p+1][1] = r4[3];
            }
            #pragma unroll
            for (int m = 0; m < 3; ++m) {
                const int m0 = rg * 48 + m * 16;
                const uint32_t aoff =
                    (uint32_t)(m0 + a_row_l) * (XPITCH * 2) + (ks * 16 + a_k_l) * 2;
                uint32_t ahi[4], alo[4];
                ldsm_x4(ahi, smem_base + XHI_OFF + aoff);
                ldsm_x4(alo, smem_base + XLO_OFF + aoff);
                #pragma unroll
                for (int n = 0; n < 4; ++n) mma_bf16(acc[m][n], ahi, bhi[n]);
                #pragma unroll
                for (int n = 0; n < 4; ++n) mma_bf16(acc[m][n], ahi, blo[n]);
                #pragma unroll
                for (int n = 0; n < 4; ++n) mma_bf16(acc[m][n], alo, bhi[n]);
            }
        }
        __syncthreads();    // x chunk buffers free for next stage
    }

    // ---- store H tiles: acc -> smem [192][132] f32 (overlays GEMM buffers) ----
    float* sH = (float*)(smc + H_OFF);
    {
        const int qr = lane >> 2;          // 0..7
        const int qc = (lane & 3) * 2;     // 0,2,4,6
        #pragma unroll
        for (int m = 0; m < 3; ++m) {
            const int row = rg * 48 + m * 16 + qr;
            #pragma unroll
            for (int n = 0; n < 4; ++n) {
                const int col = cg * 32 + n * 8 + qc;
                *(float2*)(sH + row * HSTRIDE + col) =
                    make_float2(acc[m][n][0], acc[m][n][1]);
                *(float2*)(sH + (row + 8) * HSTRIDE + col) =
                    make_float2(acc[m][n][2], acc[m][n][3]);
            }
        }
    }
    float* sA   = (float*)(smc + SA_OFF);
    float* sAdj = (float*)(smc + SADJ_OFF);
    float* sS1  = (float*)(smc + SS1_OFF);
    float* sS2  = (float*)(smc + SS2_OFF);
    float* sAl  = (float*)(smc + SAL_OFF);
    if (tid < 2 * DD) sA[tid] = a[tid];
    if (tid < NN * NN) sAdj[tid] = adj[tid];
    __syncthreads();

    // ---- s1 = H @ a[:D], s2 = H @ a[D:] : 12 rows per warp ----
    {
        #pragma unroll
        for (int pi = 0; pi < ROWS / 16; ++pi) {
            const int p = wid * (ROWS / 16) + pi;
            const float* hrow = sH + p * HSTRIDE;
            float v1 = 0.f, v2 = 0.f;
            #pragma unroll
            for (int dd = 0; dd < DD; dd += 32) {
                float h = hrow[dd + lane];
                v1 = fmaf(h, sA[dd + lane], v1);
                v2 = fmaf(h, sA[DD + dd + lane], v2);
            }
            #pragma unroll
            for (int o = 16; o > 0; o >>= 1) {
                v1 += __shfl_xor_sync(0xffffffffu, v1, o);
                v2 += __shfl_xor_sync(0xffffffffu, v2, o);
            }
            if (lane == 0) { sS1[p] = v1; sS2[p] = v2; }
        }
    }
    __syncthreads();

    // ---- masked softmax: threads 0..191 ----
    if (tid < ROWS) {
        const int pb = tid / NN, i = tid % NN;
        const float si = sS2[tid];
        float e[NN];
        float m = -1e30f;
        #pragma unroll
        for (int j = 0; j < NN; ++j) {
            float v = si + sS1[pb * NN + j];
            v = v >= 0.f ? v : 0.2f * v;                  // leaky_relu 0.2
            e[j] = (sAdj[i * NN + j] == 1.0f) ? v : -1e30f;
            m = fmaxf(m, e[j]);
        }
        float s = 0.f;
        #pragma unroll
        for (int j = 0; j < NN; ++j) {
            float p_ = (e[j] > -1e29f) ? __expf(e[j] - m) : 0.f;
            e[j] = p_;
            s += p_;
        }
        const float inv = 1.0f / s;
        #pragma unroll
        for (int j = 0; j < NN; ++j)
            sAl[tid * NN + j] = e[j] * inv;
    }
    __syncthreads();

    // ---- h' = alpha @ H, elu, store. Each warp: 1 b, H[b] cached in regs ----
    {
        const int d0 = lane * 4;
        const int b = wid;                    // 0..15
        const int rowb = b * NN;
        float4 h[NN];
        #pragma unroll
        for (int j = 0; j < NN; ++j)
            h[j] = *(const float4*)(sH + (rowb + j) * HSTRIDE + d0);
        #pragma unroll
        for (int i = 0; i < NN; ++i) {
            const float* al = sAl + (rowb + i) * NN;
            float4 o4 = make_float4(0.f, 0.f, 0.f, 0.f);
            #pragma unroll
            for (int j = 0; j < NN; ++j) {
                const float aij = al[j];
                o4.x = fmaf(aij, h[j].x, o4.x);
                o4.y = fmaf(aij, h[j].y, o4.y);
                o4.z = fmaf(aij, h[j].z, o4.z);
                o4.w = fmaf(aij, h[j].w, o4.w);
            }
            o4.x = o4.x > 0.f ? o4.x : (__expf(o4.x) - 1.f);
            o4.y = o4.y > 0.f ? o4.y : (__expf(o4.y) - 1.f);
            o4.z = o4.z > 0.f ? o4.z : (__expf(o4.z) - 1.f);
            o4.w = o4.w > 0.f ? o4.w : (__expf(o4.w) - 1.f);
            *(float4*)(out + ((size_t)(b0 + b) * NN + i) * DD + d0) = o4;
        }
    }
}

extern "C" void kernel_launch(void* const* d_in, const int* in_sizes, int n_in,
                              void* d_out, int out_size)
{
    const float* x   = (const float*)d_in[0];
    const float* adj = (const float*)d_in[1];
    const float* W   = (const float*)d_in[2];
    const float* a   = (const float*)d_in[3];
    float* out = (float*)d_out;

    static int configured = 0;
    if (!configured) {
        cudaFuncSetAttribute(gat_hmma16_kernel,
                             cudaFuncAttributeMaxDynamicSharedMemorySize, SMEM_BYTES);
        configured = 1;
    }
    gat_hmma16_kernel<<<GRID, NTH, SMEM_BYTES>>>(x, adj, W, a, out);
}

// round 9
// speedup vs baseline: 2.9887x; 1.1360x over previous
#include <cuda_runtime.h>
#include <cuda_bf16.h>
#include <math.h>
#include <stdint.h>

// GAT layer, GB300 (base-ISA: mma.sync bf16 split GEMM).
// B=32768, N=12, F=256, D=128, fp32 in/out.
// R7: occupancy-2 design. Pre-split W kernel (f32 -> bf16 hi/lo gmem), main
// kernel BBATCH=8 / 512 thr / <=64 regs, W chunks double-buffered via cp.async.

#define NN      12
#define FF      256
#define DD      128
#define BBATCH  8
#define ROWS    96           // BBATCH * NN
#define NTH     512
#define GRID    4096         // 32768 / 8
#define KC      64
#define NCHUNK  4            // FF / KC

#define XPITCH_B  144        // bytes per x row (64 bf16 = 128B + 16B pad)
#define WPITCH_B  144        // bytes per W^T row per chunk

// ---- smem byte offsets (phase 1) ----
#define XHI_OFF  0                     // [96][144B] = 13824
#define XLO_OFF  13824
#define WBUF_OFF 27648                 // 2 bufs x (hi 18432 + lo 18432) = 73728
#define WBUF_SZ  36864
#define WLO_REL  18432
#define SMEM_BYTES 101376
// ---- phase 2 overlay ----
#define H_OFF     0                    // [96][132] f32 = 50688
#define HSTRIDE   132
#define SA_OFF    50688
#define SADJ_OFF  51712
#define SS1_OFF   52288
#define SS2_OFF   52672
#define SAL_OFF   53056                // [96][12] f32

#define XLD_ITERS 3                    // (96*16)/512 float4 loads per thread per chunk

// pre-split W: [128 n][256 k] bf16, row = 512 B
__device__ __nv_bfloat16 Whi_g[DD * FF];
__device__ __nv_bfloat16 Wlo_g[DD * FF];

static __device__ __forceinline__ uint32_t smem_addr_u32(const void* p) {
    uint32_t r;
    asm("{ .reg .u64 t; cvta.to.shared.u64 t, %1; cvt.u32.u64 %0, t; }" : "=r"(r) : "l"(p));
    return r;
}

static __device__ __forceinline__ uint32_t pack_bf2(__nv_bfloat16 a, __nv_bfloat16 b) {
    __nv_bfloat162 h; h.x = a; h.y = b;
    return *reinterpret_cast<uint32_t*>(&h);
}

static __device__ __forceinline__ void split_f32(float v, __nv_bfloat16& hi, __nv_bfloat16& lo) {
    hi = __float2bfloat16_rn(v);
    lo = __float2bfloat16_rn(v - __bfloat162float(hi));
}

static __device__ __forceinline__ void ldsm_x4(uint32_t* r, uint32_t addr) {
    asm volatile("ldmatrix.sync.aligned.m8n8.x4.shared.b16 {%0,%1,%2,%3}, [%4];"
                 : "=r"(r[0]), "=r"(r[1]), "=r"(r[2]), "=r"(r[3]) : "r"(addr));
}

static __device__ __forceinline__ void mma_bf16(float* d, const uint32_t* a, const uint32_t* b) {
    asm volatile(
        "mma.sync.aligned.m16n8k16.row.col.f32.bf16.bf16.f32 "
        "{%0,%1,%2,%3}, {%4,%5,%6,%7}, {%8,%9}, {%0,%1,%2,%3};"
        : "+f"(d[0]), "+f"(d[1]), "+f"(d[2]), "+f"(d[3])
        : "r"(a[0]), "r"(a[1]), "r"(a[2]), "r"(a[3]), "r"(b[0]), "r"(b[1]));
}

static __device__ __forceinline__ void cp16(uint32_t dst, const void* src) {
    asm volatile("cp.async.ca.shared.global [%0], [%1], 16;" :: "r"(dst), "l"(src) : "memory");
}

// ---- kernel 1: split W into bf16 hi/lo, transposed to [n][k] ----
__global__ void gat_wsplit_kernel(const float* __restrict__ W)
{
    const int k = blockIdx.x;          // 0..255
    const int n = threadIdx.x;         // 0..127
    float v = W[(size_t)k * DD + n];   // coalesced read
    __nv_bfloat16 hi, lo;
    split_f32(v, hi, lo);
    Whi_g[(size_t)n * FF + k] = hi;
    Wlo_g[(size_t)n * FF + k] = lo;
}

extern __shared__ __align__(1024) char smc[];

__global__ __launch_bounds__(NTH, 2)
void gat_hmma8_kernel(const float* __restrict__ x,
                      const float* __restrict__ adj,
                      const float* __restrict__ a,
                      float* __restrict__ out)
{
    const int tid  = threadIdx.x;
    const int wid  = tid >> 5;
    const int lane = tid & 31;
    const int b0   = blockIdx.x * BBATCH;

    const uint32_t smem_base = smem_addr_u32(smc);

    const float4* xg4 = (const float4*)x;
    const size_t rowbase4 = (size_t)b0 * NN * (FF / 4);

    // W chunk cp.async: 2048 16B units per chunk (hi+lo), 4 per thread
    // u = tid + i*512: pol = u>>10, n = (u&1023)>>3, c16 = u&7
    const __nv_bfloat16* wsrc_base[2] = { Whi_g, Wlo_g };

    // ---- prologue: W chunk0 cp.async, x chunk0 reg prefetch ----
    #pragma unroll
    for (int i = 0; i < 4; ++i) {
        const int u = tid + i * NTH;
        const int pol = u >> 10, rem = u & 1023;
        const int n = rem >> 3, c16 = rem & 7;
        const uint32_t dst = smem_base + WBUF_OFF + pol * WLO_REL +
                             (uint32_t)n * WPITCH_B + c16 * 16;
        cp16(dst, (const char*)(wsrc_base[pol] + (size_t)n * FF) + c16 * 16);
    }
    asm volatile("cp.async.commit_group;" ::: "memory");

    float4 px[XLD_ITERS];
    #pragma unroll
    for (int i = 0; i < XLD_ITERS; ++i) {
        const int idx = tid + i * NTH;
        const int r = idx >> 4, c4 = idx & 15;
        px[i] = xg4[rowbase4 + (size_t)r * (FF / 4) + c4];
    }

    // ---- GEMM: 16 warps, warp tile 48 rows x 16 cols ----
    const int rg = wid & 1;      // rows rg*48..+48
    const int cg = wid >> 1;     // cols cg*16..+16

    float acc[3][2][4];
    #pragma unroll
    for (int m = 0; m < 3; ++m)
        #pragma unroll
        for (int n = 0; n < 2; ++n)
            #pragma unroll
            for (int q = 0; q < 4; ++q) acc[m][n][q] = 0.f;

    const int a_row_l = (lane & 7) + ((lane >> 3) & 1) * 8;
    const int a_k_l   = (lane >> 4) * 8;
    const int b_n_l   = (lane & 7) + (lane >> 4) * 8;
    const int b_k_l   = ((lane >> 3) & 1) * 8;

    for (int c = 0; c < NCHUNK; ++c) {
        // convert prefetched x chunk -> smem hi/lo
        #pragma unroll
        for (int i = 0; i < XLD_ITERS; ++i) {
            const int idx = tid + i * NTH;
            const int r = idx >> 4, c4 = idx & 15;
            float4 v = px[i];
            __nv_bfloat16 hx, lx, hy, ly, hz, lz, hw, lw;
            split_f32(v.x, hx, lx); split_f32(v.y, hy, ly);
            split_f32(v.z, hz, lz); split_f32(v.w, hw, lw);
            const uint32_t off = (uint32_t)r * XPITCH_B + c4 * 8;
            *(uint2*)(smc + XHI_OFF + off) = make_uint2(pack_bf2(hx, hy), pack_bf2(hz, hw));
            *(uint2*)(smc + XLO_OFF + off) = make_uint2(pack_bf2(lx, ly), pack_bf2(lz, lw));
        }
        // issue next W chunk + next x prefetch
        if (c + 1 < NCHUNK) {
            const int nb = (c + 1) & 1;
            #pragma unroll
            for (int i = 0; i < 4; ++i) {
                const int u = tid + i * NTH;
                const int pol = u >> 10, rem = u & 1023;
                const int n = rem >> 3, c16 = rem & 7;
                const uint32_t dst = smem_base + WBUF_OFF + nb * WBUF_SZ + pol * WLO_REL +
                                     (uint32_t)n * WPITCH_B + c16 * 16;
                cp16(dst, (const char*)(wsrc_base[pol] + (size_t)n * FF + (c + 1) * KC) + c16 * 16);
            }
            asm volatile("cp.async.commit_group;" ::: "memory");
            #pragma unroll
            for (int i = 0; i < XLD_ITERS; ++i) {
                const int idx = tid + i * NTH;
                const int r = idx >> 4, c4 = idx & 15;
                px[i] = xg4[rowbase4 + (size_t)r * (FF / 4) + (c + 1) * (KC / 4) + c4];
            }
            asm volatile("cp.async.wait_group 1;" ::: "memory");
        } else {
            asm volatile("cp.async.wait_group 0;" ::: "memory");
        }
        __syncthreads();

        const uint32_t wbuf = smem_base + WBUF_OFF + (c & 1) * WBUF_SZ;
        #pragma unroll
        for (int ks = 0; ks < KC / 16; ++ks) {
            // B fragments: 2 n8-tiles, hi & lo (one x4 each)
            const uint32_t boff = (uint32_t)(cg * 16 + b_n_l) * WPITCH_B +
                                  (ks * 16 + b_k_l) * 2;
            uint32_t bhi[4], blo[4];
            ldsm_x4(bhi, wbuf + boff);
            ldsm_x4(blo, wbuf + WLO_REL + boff);
            #pragma unroll
            for (int m = 0; m < 3; ++m) {
                const int m0 = rg * 48 + m * 16;
                const uint32_t aoff = (uint32_t)(m0 + a_row_l) * XPITCH_B +
                                      (ks * 16 + a_k_l) * 2;
                uint32_t ahi[4], alo[4];
                ldsm_x4(ahi, smem_base + XHI_OFF + aoff);
                ldsm_x4(alo, smem_base + XLO_OFF + aoff);
                mma_bf16(acc[m][0], ahi, bhi + 0);
                mma_bf16(acc[m][1], ahi, bhi + 2);
                mma_bf16(acc[m][0], ahi, blo + 0);
                mma_bf16(acc[m][1], ahi, blo + 2);
                mma_bf16(acc[m][0], alo, bhi + 0);
                mma_bf16(acc[m][1], alo, bhi + 2);
            }
        }
        __syncthreads();
    }

    // ---- store H tiles: acc -> smem [96][132] f32 ----
    float* sH = (float*)(smc + H_OFF);
    {
        const int qr = lane >> 2;
        const int qc = (lane & 3) * 2;
        #pragma unroll
        for (int m = 0; m < 3; ++m) {
            const int row = rg * 48 + m * 16 + qr;
            #pragma unroll
            for (int n = 0; n < 2; ++n) {
                const int col = cg * 16 + n * 8 + qc;
                *(float2*)(sH + row * HSTRIDE + col) =
                    make_float2(acc[m][n][0], acc[m][n][1]);
                *(float2*)(sH + (row + 8) * HSTRIDE + col) =
                    make_float2(acc[m][n][2], acc[m][n][3]);
            }
        }
    }
    float* sA   = (float*)(smc + SA_OFF);
    float* sAdj = (float*)(smc + SADJ_OFF);
    float* sS1  = (float*)(smc + SS1_OFF);
    float* sS2  = (float*)(smc + SS2_OFF);
    float* sAl  = (float*)(smc + SAL_OFF);
    if (tid < 2 * DD) sA[tid] = a[tid];
    if (tid < NN * NN) sAdj[tid] = adj[tid];
    __syncthreads();

    // ---- s1/s2: 6 rows per warp ----
    {
        #pragma unroll
        for (int pi = 0; pi < ROWS / 16; ++pi) {
            const int p = wid * (ROWS / 16) + pi;
            const float* hrow = sH + p * HSTRIDE;
            float v1 = 0.f, v2 = 0.f;
            #pragma unroll
            for (int dd = 0; dd < DD; dd += 32) {
                float h = hrow[dd + lane];
                v1 = fmaf(h, sA[dd + lane], v1);
                v2 = fmaf(h, sA[DD + dd + lane], v2);
            }
            #pragma unroll
            for (int o = 16; o > 0; o >>= 1) {
                v1 += __shfl_xor_sync(0xffffffffu, v1, o);
                v2 += __shfl_xor_sync(0xffffffffu, v2, o);
            }
            if (lane == 0) { sS1[p] = v1; sS2[p] = v2; }
        }
    }
    __syncthreads();

    // ---- masked softmax: threads 0..95 ----
    if (tid < ROWS) {
        const int pb = tid / NN, i = tid % NN;
        const float si = sS2[tid];
        float e[NN];
        float m = -1e30f;
        #pragma unroll
        for (int j = 0; j < NN; ++j) {
            float v = si + sS1[pb * NN + j];
            v = v >= 0.f ? v : 0.2f * v;                  // leaky_relu 0.2
            e[j] = (sAdj[i * NN + j] == 1.0f) ? v : -1e30f;
            m = fmaxf(m, e[j]);
        }
        float s = 0.f;
        #pragma unroll
        for (int j = 0; j < NN; ++j) {
            float p_ = (e[j] > -1e29f) ? __expf(e[j] - m) : 0.f;
            e[j] = p_;
            s += p_;
        }
        const float inv = 1.0f / s;
        #pragma unroll
        for (int j = 0; j < NN; ++j)
            sAl[tid * NN + j] = e[j] * inv;
    }
    __syncthreads();

    // ---- h' = alpha @ H, elu, store: warp -> (b = wid>>1, d-half = wid&1) ----
    {
        const int b  = wid >> 1;
        const int dh = wid & 1;
        const int col0 = dh * 64 + lane * 2;
        const int rowb = b * NN;
        float2 h[NN];
        #pragma unroll
        for (int j = 0; j < NN; ++j)
            h[j] = *(const float2*)(sH + (rowb + j) * HSTRIDE + col0);
        #pragma unroll
        for (int i = 0; i < NN; ++i) {
            const float* al = sAl + (rowb + i) * NN;
            float2 o2 = make_float2(0.f, 0.f);
            #pragma unroll
            for (int j = 0; j < NN; ++j) {
                const float aij = al[j];
                o2.x = fmaf(aij, h[j].x, o2.x);
                o2.y = fmaf(aij, h[j].y, o2.y);
            }
            o2.x = o2.x > 0.f ? o2.x : (__expf(o2.x) - 1.f);
            o2.y = o2.y > 0.f ? o2.y : (__expf(o2.y) - 1.f);
            *(float2*)(out + ((size_t)(b0 + b) * NN + i) * DD + col0) = o2;
        }
    }
}

extern "C" void kernel_launch(void* const* d_in, const int* in_sizes, int n_in,
                              void* d_out, int out_size)
{
    const float* x   = (const float*)d_in[0];
    const float* adj = (const float*)d_in[1];
    const float* W   = (const float*)d_in[2];
    const float* a   = (const float*)d_in[3];
    float* out = (float*)d_out;

    static int configured = 0;
    if (!configured) {
        cudaFuncSetAttribute(gat_hmma8_kernel,
                             cudaFuncAttributeMaxDynamicSharedMemorySize, SMEM_BYTES);
        configured = 1;
    }
    gat_wsplit_kernel<<<FF, DD>>>(W);
    gat_hmma8_kernel<<<GRID, NTH, SMEM_BYTES>>>(x, adj, a, out);
}